// round 6
// baseline (speedup 1.0000x reference)
#include <cuda_runtime.h>
#include <cstdint>

// Problem constants
#define QB   64
#define QH   8
#define QM   1024
#define QC   128
#define QMID 64
#define TM   128                  // rows per kf tile
#define NTILES (QM / TM)          // 8
#define NTHREADS 256

// packed fp32x2 FMA (Blackwell): d = a*b + d on both lanes
__device__ __forceinline__ void ffma2(unsigned long long &d, unsigned long long a, unsigned long long b) {
    asm volatile("fma.rn.f32x2 %0, %1, %2, %0;" : "+l"(d) : "l"(a), "l"(b));
}
__device__ __forceinline__ unsigned long long splat2(float v) {
    unsigned long long r;
    asm("mov.b64 %0, {%1, %1};" : "=l"(r) : "f"(v));
    return r;
}
__device__ __forceinline__ float2 unpack2(unsigned long long v) {
    float2 r;
    asm("mov.b64 {%0, %1}, %2;" : "=f"(r.x), "=f"(r.y) : "l"(v));
    return r;
}
static __device__ __forceinline__ uint32_t smem_u32(const void* p) {
    uint32_t a;
    asm("{ .reg .u64 t; cvta.to.shared.u64 t, %1; cvt.u32.u64 %0, t; }" : "=r"(a) : "l"(p));
    return a;
}
static __device__ __forceinline__ void cp_async16(uint32_t dst, const void* src) {
    asm volatile("cp.async.cg.shared.global [%0], [%1], 16;" :: "r"(dst), "l"(src) : "memory");
}
#define CP_COMMIT() asm volatile("cp.async.commit_group;" ::: "memory")
#define CP_WAIT0()  asm volatile("cp.async.wait_group 0;" ::: "memory")

// dynamic smem layout (floats):
//  wq      : 128*64  = 8192   (phase2: partial buffer 8x128)
//  kf      : 128*128 = 16384  (att partials [128x64] alias the BACK half: rows 64-127)
//  logit   : 1024
//  maskf   : 1024
//  wl/bb/pool : 64*3
//  red     : 128  (q staging)
//  sc      : 40
#define SMEM_FLOATS (8192 + 16384 + 1024 + 1024 + 64 + 64 + 64 + 128 + 40)

extern "C" __global__ void __launch_bounds__(NTHREADS, 2)
scatt_kernel(const float* __restrict__ query,
             const float* __restrict__ key_feat,
             const int*   __restrict__ att_mask,
             const float* __restrict__ value1,
             const float* __restrict__ value2,
             const float* __restrict__ w_basic,
             const float* __restrict__ b_basic,
             const float* __restrict__ w_last,
             const float* __restrict__ b_last,
             const float* __restrict__ w_last2,
             const float* __restrict__ b_last2,
             float* __restrict__ out)
{
    extern __shared__ float sm[];
    float* wq_s    = sm;                      // [k][o]  k:128 o:64
    float* kf_s    = wq_s + 8192;             // [m][quad-swizzled k], 128x128
    float* att_s   = kf_s + 8192;             // ALIAS of kf BACK half: 128x64 partials
    float* logit_s = kf_s + 16384;            // 1024
    float* maskf_s = logit_s + 1024;          // 1024
    float* wl_s    = maskf_s + 1024;          // 64
    float* bb_s    = wl_s + 64;               // 64
    float* pool_s  = bb_s + 64;               // 64
    float* red_s   = pool_s + 64;             // 128 (q staging)
    float* sc_s    = red_s + 128;             // 40
    int*   cnt_i   = (int*)(sc_s + 35);

    const uint32_t kf_addr = smem_u32(kf_s);

    const int tid = threadIdx.x;
    const int bh  = blockIdx.x;
    const int b   = bh >> 3;
    const int h   = bh & 7;

    const float* qp  = query    + bh * QC;
    const float* kfp = key_feat + (size_t)bh * QM * QC;

    // staging helper constants: thread's float4 slots f = tid + it*256;
    // it 0..7 -> rows 0..63 (lo), it 8..15 -> rows 64..127 (hi)
    // quad-swizzle: qs = qk ^ ((m>>3)&7)

    // ---------------- prefetch tile 0 (both halves) ----------------
    {
        const float* src = kfp;               // tile 0
        #pragma unroll
        for (int it = 0; it < 16; ++it) {
            int f  = tid + it * NTHREADS;
            int m  = f >> 5;
            int qk = f & 31;
            int qs = qk ^ ((m >> 3) & 7);
            cp_async16(kf_addr + (uint32_t)(((m << 7) + (qs << 2)) << 2),
                       src + (m << 7) + (qk << 2));
        }
        CP_COMMIT();
    }

    // ---------------- setup (overlaps tile-0 staging) ----------------
    if (tid == 0) *cnt_i = 0;
    if (tid < 64) {
        pool_s[tid] = 0.f;
        wl_s[tid]   = w_last[h * QMID + tid];
        bb_s[tid]   = b_basic[h * QMID + tid];
    }
    int cl = 0;
    for (int i = tid; i < QM; i += NTHREADS) {
        int mv = att_mask[b * QM + i];
        maskf_s[i] = (float)mv;
        cl += mv;
    }
    for (int i = tid; i < QC; i += NTHREADS) red_s[i] = qp[i];
    __syncthreads();

    // wq[k][o] = q[k] * w_basic[h][k][o]
    for (int i = tid; i < QC * QMID; i += NTHREADS) {
        int k = i >> 6;
        wq_s[i] = red_s[k] * w_basic[(h * QC + k) * QMID + (i & 63)];
    }
    #pragma unroll
    for (int o = 16; o; o >>= 1) cl += __shfl_xor_sync(~0u, cl, o);
    if ((tid & 31) == 0) atomicAdd(cnt_i, cl);

    const float blast = b_last[h];

    // thread decomposition for GEMM (split-K: 2 groups x 128 threads)
    const int g  = tid >> 7;        // split-K group (0: k<64, 1: k>=64)
    const int t  = tid & 127;
    const int rg = t >> 3;          // 0..15 (8 rows each -> 128 rows)
    const int cg = t & 7;           // 0..7  (cols {4cg..4cg+3} u {32+4cg..+3})
    const int xc = rg & 7;          // kf quad swizzle key
    const int qa = cg ^ (rg & 3);   // att_s swizzled quad

    float pp[8] = {0.f, 0.f, 0.f, 0.f, 0.f, 0.f, 0.f, 0.f};

    CP_WAIT0();        // tile 0 resident
    __syncthreads();

    // ---------------- main tiles (pipelined staging) ----------------
    for (int tile = 0; tile < NTILES; ++tile) {
        // ---- GEMM on tile (split-K, this group's k-range [g*64, g*64+64)) ----
        unsigned long long acc[8][4];
        #pragma unroll
        for (int r = 0; r < 8; ++r)
            #pragma unroll
            for (int c = 0; c < 4; ++c) acc[r][c] = 0ULL;

        const float* kfb = kf_s + (rg << 3) * QC;

        #pragma unroll 1
        for (int q = 0; q < 16; ++q) {
            const int qq = (g << 4) + q;        // global quad 0..31
            float4 a[8];
            const int qs4 = ((qq ^ xc) << 2);
            #pragma unroll
            for (int r = 0; r < 8; ++r)
                a[r] = *(const float4*)(kfb + (r << 7) + qs4);

            #pragma unroll
            for (int j = 0; j < 4; ++j) {
                const float* wr = wq_s + ((qq << 2) + j) * QMID + (cg << 2);
                ulonglong2 bv0 = *(const ulonglong2*)wr;
                ulonglong2 bv1 = *(const ulonglong2*)(wr + 32);
                #pragma unroll
                for (int r = 0; r < 8; ++r) {
                    float av = (j == 0) ? a[r].x : (j == 1) ? a[r].y : (j == 2) ? a[r].z : a[r].w;
                    unsigned long long ap = splat2(av);
                    ffma2(acc[r][0], ap, bv0.x);
                    ffma2(acc[r][1], ap, bv0.y);
                    ffma2(acc[r][2], ap, bv1.x);
                    ffma2(acc[r][3], ap, bv1.y);
                }
            }
        }

        __syncthreads();   // all kf reads finished

        // ---- issue lo-half staging of next tile (rows 0..63) -> kf front ----
        const float* nsrc = kfp + (size_t)(tile + 1) * TM * QC;
        if (tile + 1 < NTILES) {
            #pragma unroll
            for (int it = 0; it < 8; ++it) {
                int f  = tid + it * NTHREADS;     // f < 2048 -> m < 64
                int m  = f >> 5;
                int qk = f & 31;
                int qs = qk ^ ((m >> 3) & 7);
                cp_async16(kf_addr + (uint32_t)(((m << 7) + (qs << 2)) << 2),
                           nsrc + (m << 7) + (qk << 2));
            }
            CP_COMMIT();
        }

        // ---- split-K combine via att_s (kf BACK half) ----
        if (g == 0) {
            #pragma unroll
            for (int r = 0; r < 8; ++r) {
                float2 p0 = unpack2(acc[r][0]);
                float2 p1 = unpack2(acc[r][1]);
                float2 p2 = unpack2(acc[r][2]);
                float2 p3 = unpack2(acc[r][3]);
                float* dst = att_s + ((rg << 3) + r) * QMID + (qa << 2);
                *(float4*)dst        = make_float4(p0.x, p0.y, p1.x, p1.y);
                *(float4*)(dst + 32) = make_float4(p2.x, p2.y, p3.x, p3.y);
            }
        }
        __syncthreads();
        if (g == 1) {
            float wl0[4], wl1[4], bb0[4], bb1[4];
            #pragma unroll
            for (int j = 0; j < 4; ++j) {
                wl0[j] = wl_s[4 * cg + j];      wl1[j] = wl_s[32 + 4 * cg + j];
                bb0[j] = bb_s[4 * cg + j];      bb1[j] = bb_s[32 + 4 * cg + j];
            }
            #pragma unroll
            for (int r = 0; r < 8; ++r) {
                const int ml = (rg << 3) + r;
                const int mg = tile * TM + ml;
                const float* srcA = att_s + ml * QMID + (qa << 2);
                float4 u0 = *(const float4*)srcA;
                float4 u1 = *(const float4*)(srcA + 32);
                float2 p0 = unpack2(acc[r][0]);
                float2 p1 = unpack2(acc[r][1]);
                float2 p2 = unpack2(acc[r][2]);
                float2 p3 = unpack2(acc[r][3]);
                float x0 = fmaxf(u0.x + p0.x + bb0[0], 0.f);
                float x1 = fmaxf(u0.y + p0.y + bb0[1], 0.f);
                float x2 = fmaxf(u0.z + p1.x + bb0[2], 0.f);
                float x3 = fmaxf(u0.w + p1.y + bb0[3], 0.f);
                float x4 = fmaxf(u1.x + p2.x + bb1[0], 0.f);
                float x5 = fmaxf(u1.y + p2.y + bb1[1], 0.f);
                float x6 = fmaxf(u1.z + p3.x + bb1[2], 0.f);
                float x7 = fmaxf(u1.w + p3.y + bb1[3], 0.f);

                float lp = x0 * wl0[0] + x1 * wl0[1] + x2 * wl0[2] + x3 * wl0[3]
                         + x4 * wl1[0] + x5 * wl1[1] + x6 * wl1[2] + x7 * wl1[3];

                float mk = maskf_s[mg];
                pp[0] += x0 * mk; pp[1] += x1 * mk; pp[2] += x2 * mk; pp[3] += x3 * mk;
                pp[4] += x4 * mk; pp[5] += x5 * mk; pp[6] += x6 * mk; pp[7] += x7 * mk;

                lp += __shfl_xor_sync(~0u, lp, 1);
                lp += __shfl_xor_sync(~0u, lp, 2);
                lp += __shfl_xor_sync(~0u, lp, 4);
                if (cg == 0) logit_s[mg] = (mk != 0.f) ? (lp + blast) : -1e9f;
            }
        }
        __syncthreads();   // epilogue reads of att (kf back half) done

        // ---- issue hi-half staging (rows 64..127) and wait both halves ----
        if (tile + 1 < NTILES) {
            #pragma unroll
            for (int it = 8; it < 16; ++it) {
                int f  = tid + it * NTHREADS;     // m >= 64
                int m  = f >> 5;
                int qk = f & 31;
                int qs = qk ^ ((m >> 3) & 7);
                cp_async16(kf_addr + (uint32_t)(((m << 7) + (qs << 2)) << 2),
                           nsrc + (m << 7) + (qk << 2));
            }
            CP_COMMIT();
            CP_WAIT0();
            __syncthreads();
        }
    }

    // pool accumulation (masked sums, still unnormalized)
    if (g == 1) {
        #pragma unroll
        for (int j = 0; j < 4; ++j) {
            atomicAdd(&pool_s[(cg << 2) + j],      pp[j]);
            atomicAdd(&pool_s[32 + (cg << 2) + j], pp[4 + j]);
        }
    }
    __syncthreads();

    // ---------------- softmax over logits ----------------
    const float cnt_inv = 1.0f / (float)(*cnt_i);
    if (tid < 64) pool_s[tid] *= cnt_inv;

    float lm = -3.4e38f;
    for (int i = tid; i < QM; i += NTHREADS) lm = fmaxf(lm, logit_s[i]);
    #pragma unroll
    for (int o = 16; o; o >>= 1) lm = fmaxf(lm, __shfl_xor_sync(~0u, lm, o));
    if ((tid & 31) == 0) sc_s[tid >> 5] = lm;
    __syncthreads();
    if (tid < 32) {
        float v = (tid < 8) ? sc_s[tid] : -3.4e38f;
        #pragma unroll
        for (int o = 4; o; o >>= 1) v = fmaxf(v, __shfl_xor_sync(~0u, v, o));
        if (tid == 0) sc_s[32] = v;
    }
    __syncthreads();
    const float gmax = sc_s[32];

    float se = 0.f;
    for (int i = tid; i < QM; i += NTHREADS) {
        float e = __expf(logit_s[i] - gmax);
        logit_s[i] = e;                   // in-place: unnormalized alpha
        se += e;
    }
    #pragma unroll
    for (int o = 16; o; o >>= 1) se += __shfl_xor_sync(~0u, se, o);
    if ((tid & 31) == 0) sc_s[tid >> 5] = se;
    __syncthreads();
    if (tid < 32) {
        float v = (tid < 8) ? sc_s[tid] : 0.f;
        #pragma unroll
        for (int o = 4; o; o >>= 1) v += __shfl_xor_sync(~0u, v, o);
        if (tid == 0) sc_s[33] = 1.0f / v;
    }
    __syncthreads();
    const float inv_se = sc_s[33];

    // ---------------- v2 = alpha^T @ value2 (8 m-slices x 32 float4 cols) ----
    {
        const int qc    = tid & 31;      // float4 column (4 d's)
        const int slice = tid >> 5;      // 0..7, 128 m each
        const float* vp = value2 + (size_t)bh * QM * QC + (size_t)(slice * 128) * QC + (qc << 2);
        const float* al = logit_s + slice * 128;
        float ax = 0.f, ay = 0.f, az = 0.f, aw = 0.f;
        #pragma unroll 8
        for (int m = 0; m < 128; ++m) {
            float a4 = al[m];
            float4 v = __ldcs((const float4*)(vp + m * QC));
            ax += a4 * v.x; ay += a4 * v.y; az += a4 * v.z; aw += a4 * v.w;
        }
        // partials into wq_s (dead now): [slice][128 d]
        *(float4*)(wq_s + slice * QC + (qc << 2)) = make_float4(ax, ay, az, aw);
    }
    __syncthreads();

    // ---------------- final reduce + channel gate + output ----------------
    if (tid < QC) {
        const int d = tid;
        float v2v = 0.f;
        #pragma unroll
        for (int s = 0; s < 8; ++s) v2v += wq_s[s * QC + d];
        v2v *= inv_se;

        const float* w2 = w_last2 + (h * QMID) * QC + d;
        float pv = 0.f;
        #pragma unroll 8
        for (int o = 0; o < QMID; ++o) pv += pool_s[o] * w2[o * QC];
        float z   = pv + b_last2[h * QC + d];
        float acv = 1.0f / (1.0f + __expf(-z));
        out[bh * QC + d] = value1[bh * QC + d] * v2v * acv;
    }
}

extern "C" void kernel_launch(void* const* d_in, const int* in_sizes, int n_in,
                              void* d_out, int out_size) {
    const float* query    = (const float*)d_in[0];
    const float* key_feat = (const float*)d_in[1];
    const int*   att_mask = (const int*)  d_in[2];
    const float* value1   = (const float*)d_in[3];
    const float* value2   = (const float*)d_in[4];
    const float* w_basic  = (const float*)d_in[5];
    const float* b_basic  = (const float*)d_in[6];
    const float* w_last   = (const float*)d_in[7];
    const float* b_last   = (const float*)d_in[8];
    const float* w_last2  = (const float*)d_in[9];
    const float* b_last2  = (const float*)d_in[10];
    float* out = (float*)d_out;

    const int smem_bytes = SMEM_FLOATS * (int)sizeof(float);
    cudaFuncSetAttribute(scatt_kernel, cudaFuncAttributeMaxDynamicSharedMemorySize, smem_bytes);
    scatt_kernel<<<QB * QH, NTHREADS, smem_bytes>>>(
        query, key_feat, att_mask, value1, value2,
        w_basic, b_basic, w_last, b_last, w_last2, b_last2, out);
}

// round 7
// speedup vs baseline: 1.0694x; 1.0694x over previous
#include <cuda_runtime.h>
#include <cstdint>

// Problem constants
#define QB   64
#define QH   8
#define QM   1024
#define QC   128
#define QMID 64
#define TM   128                  // rows per kf tile
#define NTILES (QM / TM)          // 8
#define NTHREADS 256

// packed fp32x2 FMA (Blackwell): d = a*b + d on both lanes
__device__ __forceinline__ void ffma2(unsigned long long &d, unsigned long long a, unsigned long long b) {
    asm volatile("fma.rn.f32x2 %0, %1, %2, %0;" : "+l"(d) : "l"(a), "l"(b));
}
__device__ __forceinline__ unsigned long long splat2(float v) {
    unsigned long long r;
    asm("mov.b64 %0, {%1, %1};" : "=l"(r) : "f"(v));
    return r;
}
__device__ __forceinline__ float2 unpack2(unsigned long long v) {
    float2 r;
    asm("mov.b64 {%0, %1}, %2;" : "=f"(r.x), "=f"(r.y) : "l"(v));
    return r;
}
static __device__ __forceinline__ uint32_t smem_u32(const void* p) {
    uint32_t a;
    asm("{ .reg .u64 t; cvta.to.shared.u64 t, %1; cvt.u32.u64 %0, t; }" : "=r"(a) : "l"(p));
    return a;
}
static __device__ __forceinline__ void cp_async16(uint32_t dst, const void* src) {
    asm volatile("cp.async.cg.shared.global [%0], [%1], 16;" :: "r"(dst), "l"(src) : "memory");
}
#define CP_COMMIT() asm volatile("cp.async.commit_group;" ::: "memory")
#define CP_WAIT0()  asm volatile("cp.async.wait_group 0;" ::: "memory")

// dynamic smem layout (floats):
//  wq      : 128*64  = 8192   (phase2: partial buffer 8x128)
//  kf      : 128*128 = 16384  (att partials [128x64] alias the front)
//  logit   : 1024
//  maskf   : 1024
//  wl/bb/pool : 64*3
//  red     : 128  (q staging)
//  sc      : 40
#define SMEM_FLOATS (8192 + 16384 + 1024 + 1024 + 64 + 64 + 64 + 128 + 40)

extern "C" __global__ void __launch_bounds__(NTHREADS, 2)
scatt_kernel(const float* __restrict__ query,
             const float* __restrict__ key_feat,
             const int*   __restrict__ att_mask,
             const float* __restrict__ value1,
             const float* __restrict__ value2,
             const float* __restrict__ w_basic,
             const float* __restrict__ b_basic,
             const float* __restrict__ w_last,
             const float* __restrict__ b_last,
             const float* __restrict__ w_last2,
             const float* __restrict__ b_last2,
             float* __restrict__ out)
{
    extern __shared__ float sm[];
    float* wq_s    = sm;                      // [k][o]  k:128 o:64
    float* kf_s    = wq_s + 8192;             // [m][quad-swizzled k], 128x128
    float* att_s   = kf_s;                    // ALIAS: 128x64 split-K partials
    float* logit_s = kf_s + 16384;            // 1024
    float* maskf_s = logit_s + 1024;          // 1024
    float* wl_s    = maskf_s + 1024;          // 64
    float* bb_s    = wl_s + 64;               // 64
    float* pool_s  = bb_s + 64;               // 64
    float* red_s   = pool_s + 64;             // 128 (q staging)
    float* sc_s    = red_s + 128;             // 40
    int*   cnt_i   = (int*)(sc_s + 35);

    const uint32_t kf_addr = smem_u32(kf_s);

    const int tid = threadIdx.x;
    const int bh  = blockIdx.x;
    const int b   = bh >> 3;
    const int h   = bh & 7;

    const float* qp  = query    + bh * QC;
    const float* kfp = key_feat + (size_t)bh * QM * QC;

    // ---------------- prefetch tile 0 (overlaps setup) ----------------
    {
        #pragma unroll
        for (int it = 0; it < 16; ++it) {
            int f  = tid + it * NTHREADS;
            int m  = f >> 5;
            int qk = f & 31;
            int qs = qk ^ ((m >> 3) & 7);
            cp_async16(kf_addr + (uint32_t)(((m << 7) + (qs << 2)) << 2),
                       kfp + (m << 7) + (qk << 2));
        }
        CP_COMMIT();
    }

    // ---------------- setup ----------------
    if (tid == 0) *cnt_i = 0;
    if (tid < 64) {
        pool_s[tid] = 0.f;
        wl_s[tid]   = w_last[h * QMID + tid];
        bb_s[tid]   = b_basic[h * QMID + tid];
    }
    int cl = 0;
    for (int i = tid; i < QM; i += NTHREADS) {
        int mv = att_mask[b * QM + i];
        maskf_s[i] = (float)mv;
        cl += mv;
    }
    for (int i = tid; i < QC; i += NTHREADS) red_s[i] = qp[i];
    __syncthreads();

    // wq[k][o] = q[k] * w_basic[h][k][o]
    for (int i = tid; i < QC * QMID; i += NTHREADS) {
        int k = i >> 6;
        wq_s[i] = red_s[k] * w_basic[(h * QC + k) * QMID + (i & 63)];
    }
    #pragma unroll
    for (int o = 16; o; o >>= 1) cl += __shfl_xor_sync(~0u, cl, o);
    if ((tid & 31) == 0) atomicAdd(cnt_i, cl);

    const float blast = b_last[h];

    // thread decomposition for GEMM (split-K: 2 groups x 128 threads)
    const int g  = tid >> 7;        // split-K group (0: k<64, 1: k>=64)
    const int t  = tid & 127;
    const int rg = t >> 3;          // 0..15 (8 rows each -> 128 rows)
    const int cg = t & 7;           // 0..7  (cols {4cg..4cg+3} u {32+4cg..+3})
    const int xc = rg & 7;          // kf quad swizzle key
    const int qa = cg ^ (rg & 3);   // att_s swizzled quad

    float pp[8] = {0.f, 0.f, 0.f, 0.f, 0.f, 0.f, 0.f, 0.f};

    // ---------------- main tiles ----------------
    for (int tile = 0; tile < NTILES; ++tile) {
        if (tile > 0) {
            __syncthreads();   // prev tile epilogue done with att_s (alias of kf)
            const float* src = kfp + (size_t)tile * TM * QC;
            #pragma unroll
            for (int it = 0; it < 16; ++it) {
                int f  = tid + it * NTHREADS;     // float4 index, 4096 total
                int m  = f >> 5;
                int qk = f & 31;
                int qs = qk ^ ((m >> 3) & 7);
                cp_async16(kf_addr + (uint32_t)(((m << 7) + (qs << 2)) << 2),
                           src + (m << 7) + (qk << 2));
            }
            CP_COMMIT();
        }
        CP_WAIT0();
        __syncthreads();

        // split-K GEMM: this group's k-range [g*64, g*64+64)
        // per q: hoist ALL B (8 LDS.128) to the front, then two 4-row A passes
        unsigned long long acc[8][4];
        #pragma unroll
        for (int r = 0; r < 8; ++r)
            #pragma unroll
            for (int c = 0; c < 4; ++c) acc[r][c] = 0ULL;

        const float* kfb = kf_s + (rg << 3) * QC;
        const float* wb  = wq_s + (g << 12) + (cg << 2);   // g*4096 + cg*4

        #pragma unroll 1
        for (int q = 0; q < 16; ++q) {
            const int qq = (g << 4) + q;        // global quad 0..31
            // B: all 4 j rows, both col-halves (32 regs)
            ulonglong2 b0[4], b1[4];
            #pragma unroll
            for (int j = 0; j < 4; ++j) {
                b0[j] = *(const ulonglong2*)(wb + j * QMID);
                b1[j] = *(const ulonglong2*)(wb + j * QMID + 32);
            }
            const int qs4 = ((qq ^ xc) << 2);
            #pragma unroll
            for (int half = 0; half < 2; ++half) {
                float4 a[4];
                #pragma unroll
                for (int r = 0; r < 4; ++r)
                    a[r] = *(const float4*)(kfb + (((half << 2) + r) << 7) + qs4);
                #pragma unroll
                for (int j = 0; j < 4; ++j) {
                    #pragma unroll
                    for (int r = 0; r < 4; ++r) {
                        float av = (j == 0) ? a[r].x : (j == 1) ? a[r].y : (j == 2) ? a[r].z : a[r].w;
                        unsigned long long ap = splat2(av);
                        const int rr = (half << 2) + r;
                        ffma2(acc[rr][0], ap, b0[j].x);
                        ffma2(acc[rr][1], ap, b0[j].y);
                        ffma2(acc[rr][2], ap, b1[j].x);
                        ffma2(acc[rr][3], ap, b1[j].y);
                    }
                }
            }
            wb += 256;      // next q: 4 k-rows * 64
        }

        __syncthreads();   // all kf reads finished before writing alias region

        if (g == 0) {
            #pragma unroll
            for (int r = 0; r < 8; ++r) {
                float2 p0 = unpack2(acc[r][0]);
                float2 p1 = unpack2(acc[r][1]);
                float2 p2 = unpack2(acc[r][2]);
                float2 p3 = unpack2(acc[r][3]);
                float* dst = att_s + ((rg << 3) + r) * QMID + (qa << 2);
                *(float4*)dst        = make_float4(p0.x, p0.y, p1.x, p1.y);
                *(float4*)(dst + 32) = make_float4(p2.x, p2.y, p3.x, p3.y);
            }
        }
        __syncthreads();
        if (g == 1) {
            float wl0[4], wl1[4], bb0[4], bb1[4];
            #pragma unroll
            for (int j = 0; j < 4; ++j) {
                wl0[j] = wl_s[4 * cg + j];      wl1[j] = wl_s[32 + 4 * cg + j];
                bb0[j] = bb_s[4 * cg + j];      bb1[j] = bb_s[32 + 4 * cg + j];
            }
            #pragma unroll
            for (int r = 0; r < 8; ++r) {
                const int ml = (rg << 3) + r;
                const int mg = tile * TM + ml;
                const float* srcA = att_s + ml * QMID + (qa << 2);
                float4 u0 = *(const float4*)srcA;
                float4 u1 = *(const float4*)(srcA + 32);
                float2 p0 = unpack2(acc[r][0]);
                float2 p1 = unpack2(acc[r][1]);
                float2 p2 = unpack2(acc[r][2]);
                float2 p3 = unpack2(acc[r][3]);
                float x0 = fmaxf(u0.x + p0.x + bb0[0], 0.f);
                float x1 = fmaxf(u0.y + p0.y + bb0[1], 0.f);
                float x2 = fmaxf(u0.z + p1.x + bb0[2], 0.f);
                float x3 = fmaxf(u0.w + p1.y + bb0[3], 0.f);
                float x4 = fmaxf(u1.x + p2.x + bb1[0], 0.f);
                float x5 = fmaxf(u1.y + p2.y + bb1[1], 0.f);
                float x6 = fmaxf(u1.z + p3.x + bb1[2], 0.f);
                float x7 = fmaxf(u1.w + p3.y + bb1[3], 0.f);

                float lp = x0 * wl0[0] + x1 * wl0[1] + x2 * wl0[2] + x3 * wl0[3]
                         + x4 * wl1[0] + x5 * wl1[1] + x6 * wl1[2] + x7 * wl1[3];

                float mk = maskf_s[mg];
                pp[0] += x0 * mk; pp[1] += x1 * mk; pp[2] += x2 * mk; pp[3] += x3 * mk;
                pp[4] += x4 * mk; pp[5] += x5 * mk; pp[6] += x6 * mk; pp[7] += x7 * mk;

                lp += __shfl_xor_sync(~0u, lp, 1);
                lp += __shfl_xor_sync(~0u, lp, 2);
                lp += __shfl_xor_sync(~0u, lp, 4);
                if (cg == 0) logit_s[mg] = (mk != 0.f) ? (lp + blast) : -1e9f;
            }
        }
    }

    // pool accumulation (masked sums, still unnormalized)
    if (g == 1) {
        #pragma unroll
        for (int j = 0; j < 4; ++j) {
            atomicAdd(&pool_s[(cg << 2) + j],      pp[j]);
            atomicAdd(&pool_s[32 + (cg << 2) + j], pp[4 + j]);
        }
    }
    __syncthreads();

    // ---------------- softmax over logits ----------------
    const float cnt_inv = 1.0f / (float)(*cnt_i);
    if (tid < 64) pool_s[tid] *= cnt_inv;

    float lm = -3.4e38f;
    for (int i = tid; i < QM; i += NTHREADS) lm = fmaxf(lm, logit_s[i]);
    #pragma unroll
    for (int o = 16; o; o >>= 1) lm = fmaxf(lm, __shfl_xor_sync(~0u, lm, o));
    if ((tid & 31) == 0) sc_s[tid >> 5] = lm;
    __syncthreads();
    if (tid < 32) {
        float v = (tid < 8) ? sc_s[tid] : -3.4e38f;
        #pragma unroll
        for (int o = 4; o; o >>= 1) v = fmaxf(v, __shfl_xor_sync(~0u, v, o));
        if (tid == 0) sc_s[32] = v;
    }
    __syncthreads();
    const float gmax = sc_s[32];

    float se = 0.f;
    for (int i = tid; i < QM; i += NTHREADS) {
        float e = __expf(logit_s[i] - gmax);
        logit_s[i] = e;                   // in-place: unnormalized alpha
        se += e;
    }
    #pragma unroll
    for (int o = 16; o; o >>= 1) se += __shfl_xor_sync(~0u, se, o);
    if ((tid & 31) == 0) sc_s[tid >> 5] = se;
    __syncthreads();
    if (tid < 32) {
        float v = (tid < 8) ? sc_s[tid] : 0.f;
        #pragma unroll
        for (int o = 4; o; o >>= 1) v += __shfl_xor_sync(~0u, v, o);
        if (tid == 0) sc_s[33] = 1.0f / v;
    }
    __syncthreads();
    const float inv_se = sc_s[33];

    // ---------------- v2 = alpha^T @ value2 (8 m-slices x 32 float4 cols) ----
    {
        const int qc    = tid & 31;      // float4 column (4 d's)
        const int slice = tid >> 5;      // 0..7, 128 m each
        const float* vp = value2 + (size_t)bh * QM * QC + (size_t)(slice * 128) * QC + (qc << 2);
        const float* al = logit_s + slice * 128;
        float ax = 0.f, ay = 0.f, az = 0.f, aw = 0.f;
        #pragma unroll 8
        for (int m = 0; m < 128; ++m) {
            float a4 = al[m];
            float4 v = __ldcs((const float4*)(vp + m * QC));
            ax += a4 * v.x; ay += a4 * v.y; az += a4 * v.z; aw += a4 * v.w;
        }
        // partials into wq_s (dead now): [slice][128 d]
        *(float4*)(wq_s + slice * QC + (qc << 2)) = make_float4(ax, ay, az, aw);
    }
    __syncthreads();

    // ---------------- final reduce + channel gate + output ----------------
    if (tid < QC) {
        const int d = tid;
        float v2v = 0.f;
        #pragma unroll
        for (int s = 0; s < 8; ++s) v2v += wq_s[s * QC + d];
        v2v *= inv_se;

        const float* w2 = w_last2 + (h * QMID) * QC + d;
        float pv = 0.f;
        #pragma unroll 8
        for (int o = 0; o < QMID; ++o) pv += pool_s[o] * w2[o * QC];
        float z   = pv + b_last2[h * QC + d];
        float acv = 1.0f / (1.0f + __expf(-z));
        out[bh * QC + d] = value1[bh * QC + d] * v2v * acv;
    }
}

extern "C" void kernel_launch(void* const* d_in, const int* in_sizes, int n_in,
                              void* d_out, int out_size) {
    const float* query    = (const float*)d_in[0];
    const float* key_feat = (const float*)d_in[1];
    const int*   att_mask = (const int*)  d_in[2];
    const float* value1   = (const float*)d_in[3];
    const float* value2   = (const float*)d_in[4];
    const float* w_basic  = (const float*)d_in[5];
    const float* b_basic  = (const float*)d_in[6];
    const float* w_last   = (const float*)d_in[7];
    const float* b_last   = (const float*)d_in[8];
    const float* w_last2  = (const float*)d_in[9];
    const float* b_last2  = (const float*)d_in[10];
    float* out = (float*)d_out;

    const int smem_bytes = SMEM_FLOATS * (int)sizeof(float);
    cudaFuncSetAttribute(scatt_kernel, cudaFuncAttributeMaxDynamicSharedMemorySize, smem_bytes);
    scatt_kernel<<<QB * QH, NTHREADS, smem_bytes>>>(
        query, key_feat, att_mask, value1, value2,
        w_basic, b_basic, w_last, b_last, w_last2, b_last2, out);
}

// round 8
// speedup vs baseline: 1.1056x; 1.0338x over previous
#include <cuda_runtime.h>
#include <cstdint>

// Problem constants
#define QB   64
#define QH   8
#define QM   1024
#define QC   128
#define QMID 64
#define TM   64                   // rows per kf tile (double-buffered)
#define NTILES (QM / TM)          // 16
#define NTHREADS 256

// packed fp32x2 FMA (Blackwell): d = a*b + d on both lanes
__device__ __forceinline__ void ffma2(unsigned long long &d, unsigned long long a, unsigned long long b) {
    asm volatile("fma.rn.f32x2 %0, %1, %2, %0;" : "+l"(d) : "l"(a), "l"(b));
}
__device__ __forceinline__ unsigned long long splat2(float v) {
    unsigned long long r;
    asm("mov.b64 %0, {%1, %1};" : "=l"(r) : "f"(v));
    return r;
}
__device__ __forceinline__ float2 unpack2(unsigned long long v) {
    float2 r;
    asm("mov.b64 {%0, %1}, %2;" : "=f"(r.x), "=f"(r.y) : "l"(v));
    return r;
}
static __device__ __forceinline__ uint32_t smem_u32(const void* p) {
    uint32_t a;
    asm("{ .reg .u64 t; cvta.to.shared.u64 t, %1; cvt.u32.u64 %0, t; }" : "=r"(a) : "l"(p));
    return a;
}
static __device__ __forceinline__ void cp_async16(uint32_t dst, const void* src) {
    asm volatile("cp.async.cg.shared.global [%0], [%1], 16;" :: "r"(dst), "l"(src) : "memory");
}
#define CP_COMMIT() asm volatile("cp.async.commit_group;" ::: "memory")
#define CP_WAIT0()  asm volatile("cp.async.wait_group 0;" ::: "memory")
#define CP_WAIT1()  asm volatile("cp.async.wait_group 1;" ::: "memory")

// dynamic smem layout (floats):
//  wq      : 128*64 = 8192   (phase2: partial buffer 8x128)
//  kf0/kf1 : 2 * 64*128 = 16384
//  logit   : 1024
//  maskf   : 1024
//  wl/bb/pool : 64*3
//  red     : 128  (q staging)
//  sc      : 40
#define SMEM_FLOATS (8192 + 16384 + 1024 + 1024 + 64 + 64 + 64 + 128 + 40)

extern "C" __global__ void __launch_bounds__(NTHREADS, 2)
scatt_kernel(const float* __restrict__ query,
             const float* __restrict__ key_feat,
             const int*   __restrict__ att_mask,
             const float* __restrict__ value1,
             const float* __restrict__ value2,
             const float* __restrict__ w_basic,
             const float* __restrict__ b_basic,
             const float* __restrict__ w_last,
             const float* __restrict__ b_last,
             const float* __restrict__ w_last2,
             const float* __restrict__ b_last2,
             float* __restrict__ out)
{
    extern __shared__ float sm[];
    float* wq_s    = sm;                      // [k][o]  k:128 o:64
    float* kf0_s   = wq_s + 8192;             // buffer 0: 64x128 quad-swizzled
    float* kf1_s   = kf0_s + 8192;            // buffer 1
    float* logit_s = kf1_s + 8192;            // 1024
    float* maskf_s = logit_s + 1024;          // 1024
    float* wl_s    = maskf_s + 1024;          // 64
    float* bb_s    = wl_s + 64;               // 64
    float* pool_s  = bb_s + 64;               // 64
    float* red_s   = pool_s + 64;             // 128 (q staging)
    float* sc_s    = red_s + 128;             // 40
    int*   cnt_i   = (int*)(sc_s + 35);

    const uint32_t kf0_addr = smem_u32(kf0_s);
    const uint32_t kf1_addr = smem_u32(kf1_s);

    const int tid = threadIdx.x;
    const int bh  = blockIdx.x;
    const int b   = bh >> 3;
    const int h   = bh & 7;

    const float* qp  = query    + bh * QC;
    const float* kfp = key_feat + (size_t)bh * QM * QC;

    // stage one 64-row tile into a buffer; swizzle key = (m>>2)&7
    // f = tid + it*256 (it 0..7): m = f>>5 (0..63), qk = f&31
    #define STAGE_TILE(TILE, BUFADDR)                                              \
        {                                                                          \
            const float* _src = kfp + (size_t)(TILE) * TM * QC;                    \
            _Pragma("unroll")                                                      \
            for (int _it = 0; _it < 8; ++_it) {                                    \
                int _f  = tid + _it * NTHREADS;                                    \
                int _m  = _f >> 5;                                                 \
                int _qk = _f & 31;                                                 \
                int _qs = _qk ^ ((_m >> 2) & 7);                                   \
                cp_async16((BUFADDR) + (uint32_t)((( _m << 7) + (_qs << 2)) << 2), \
                           _src + (_m << 7) + (_qk << 2));                         \
            }                                                                      \
            CP_COMMIT();                                                           \
        }

    // ---------------- prefetch tile 0 (overlaps setup) ----------------
    STAGE_TILE(0, kf0_addr);

    // ---------------- setup ----------------
    if (tid == 0) *cnt_i = 0;
    if (tid < 64) {
        pool_s[tid] = 0.f;
        wl_s[tid]   = w_last[h * QMID + tid];
        bb_s[tid]   = b_basic[h * QMID + tid];
    }
    int cl = 0;
    for (int i = tid; i < QM; i += NTHREADS) {
        int mv = att_mask[b * QM + i];
        maskf_s[i] = (float)mv;
        cl += mv;
    }
    for (int i = tid; i < QC; i += NTHREADS) red_s[i] = qp[i];
    __syncthreads();

    // wq[k][o] = q[k] * w_basic[h][k][o]
    for (int i = tid; i < QC * QMID; i += NTHREADS) {
        int k = i >> 6;
        wq_s[i] = red_s[k] * w_basic[(h * QC + k) * QMID + (i & 63)];
    }
    #pragma unroll
    for (int o = 16; o; o >>= 1) cl += __shfl_xor_sync(~0u, cl, o);
    if ((tid & 31) == 0) atomicAdd(cnt_i, cl);

    const float blast = b_last[h];

    // thread decomposition: 16 rowgroups (x4 rows) x 16 colgroups (x4 cols), full k
    const int rw = tid >> 4;        // 0..15 -> rows rw*4..rw*4+3
    const int cw = tid & 15;        // 0..15 -> cols cw*4..cw*4+3
    const int xc = rw & 7;          // A swizzle key ((m>>2)&7 == rw for m=4rw+r)

    __syncthreads();   // wq ready before GEMM reads it

    // hoisted epilogue constants
    float bb4[4], wl4[4];
    #pragma unroll
    for (int j = 0; j < 4; ++j) {
        bb4[j] = bb_s[(cw << 2) + j];
        wl4[j] = wl_s[(cw << 2) + j];
    }
    float pp[4] = {0.f, 0.f, 0.f, 0.f};

    const float* wb = wq_s + (cw << 2);

    // ---------------- main tiles (double-buffered) ----------------
    for (int tile = 0; tile < NTILES; ++tile) {
        const float* buf = (tile & 1) ? kf1_s : kf0_s;

        if (tile + 1 < NTILES) {
            STAGE_TILE(tile + 1, (tile & 1) ? kf0_addr : kf1_addr);
            CP_WAIT1();     // tile's own group done; next tile's in flight
        } else {
            CP_WAIT0();
        }
        __syncthreads();

        // full-k GEMM: 4 rows x 4 cols per thread, 32 k-quads
        unsigned long long acc[4][2];
        #pragma unroll
        for (int r = 0; r < 4; ++r) { acc[r][0] = 0ULL; acc[r][1] = 0ULL; }

        const float* kfb = buf + (rw << 9);   // rw*4 rows * 128

        #pragma unroll 2
        for (int qq = 0; qq < 32; ++qq) {
            ulonglong2 bv[4];
            #pragma unroll
            for (int j = 0; j < 4; ++j)
                bv[j] = *(const ulonglong2*)(wb + ((qq << 2) + j) * QMID);

            float4 a[4];
            const int qs4 = ((qq ^ xc) << 2);
            #pragma unroll
            for (int r = 0; r < 4; ++r)
                a[r] = *(const float4*)(kfb + (r << 7) + qs4);

            #pragma unroll
            for (int j = 0; j < 4; ++j) {
                #pragma unroll
                for (int r = 0; r < 4; ++r) {
                    float av = (j == 0) ? a[r].x : (j == 1) ? a[r].y : (j == 2) ? a[r].z : a[r].w;
                    unsigned long long ap = splat2(av);
                    ffma2(acc[r][0], ap, bv[j].x);
                    ffma2(acc[r][1], ap, bv[j].y);
                }
            }
        }

        // register epilogue: relu + bias, pool partials, logit via shuffle
        #pragma unroll
        for (int r = 0; r < 4; ++r) {
            const int mg = tile * TM + (rw << 2) + r;
            const float mk = maskf_s[mg];
            float2 lo = unpack2(acc[r][0]);
            float2 hi = unpack2(acc[r][1]);
            float x0 = fmaxf(lo.x + bb4[0], 0.f);
            float x1 = fmaxf(lo.y + bb4[1], 0.f);
            float x2 = fmaxf(hi.x + bb4[2], 0.f);
            float x3 = fmaxf(hi.y + bb4[3], 0.f);
            pp[0] += x0 * mk; pp[1] += x1 * mk; pp[2] += x2 * mk; pp[3] += x3 * mk;
            float lp = x0 * wl4[0] + x1 * wl4[1] + x2 * wl4[2] + x3 * wl4[3];
            lp += __shfl_xor_sync(~0u, lp, 1);
            lp += __shfl_xor_sync(~0u, lp, 2);
            lp += __shfl_xor_sync(~0u, lp, 4);
            lp += __shfl_xor_sync(~0u, lp, 8);
            if (cw == 0) logit_s[mg] = (mk != 0.f) ? (lp + blast) : -1e9f;
        }
        __syncthreads();   // GEMM reads of buf done before tile+2 staging overwrites it
    }

    // pool accumulation: combine rw-pairs within warp, then atomics from lanes 0-15
    #pragma unroll
    for (int j = 0; j < 4; ++j) {
        float v = pp[j];
        v += __shfl_xor_sync(~0u, v, 16);
        if ((tid & 31) < 16) atomicAdd(&pool_s[(cw << 2) + j], v);
    }
    __syncthreads();

    // ---------------- softmax over logits ----------------
    const float cnt_inv = 1.0f / (float)(*cnt_i);
    if (tid < 64) pool_s[tid] *= cnt_inv;

    float lm = -3.4e38f;
    for (int i = tid; i < QM; i += NTHREADS) lm = fmaxf(lm, logit_s[i]);
    #pragma unroll
    for (int o = 16; o; o >>= 1) lm = fmaxf(lm, __shfl_xor_sync(~0u, lm, o));
    if ((tid & 31) == 0) sc_s[tid >> 5] = lm;
    __syncthreads();
    if (tid < 32) {
        float v = (tid < 8) ? sc_s[tid] : -3.4e38f;
        #pragma unroll
        for (int o = 4; o; o >>= 1) v = fmaxf(v, __shfl_xor_sync(~0u, v, o));
        if (tid == 0) sc_s[32] = v;
    }
    __syncthreads();
    const float gmax = sc_s[32];

    float se = 0.f;
    for (int i = tid; i < QM; i += NTHREADS) {
        float e = __expf(logit_s[i] - gmax);
        logit_s[i] = e;                   // in-place: unnormalized alpha
        se += e;
    }
    #pragma unroll
    for (int o = 16; o; o >>= 1) se += __shfl_xor_sync(~0u, se, o);
    if ((tid & 31) == 0) sc_s[tid >> 5] = se;
    __syncthreads();
    if (tid < 32) {
        float v = (tid < 8) ? sc_s[tid] : 0.f;
        #pragma unroll
        for (int o = 4; o; o >>= 1) v += __shfl_xor_sync(~0u, v, o);
        if (tid == 0) sc_s[33] = 1.0f / v;
    }
    __syncthreads();
    const float inv_se = sc_s[33];

    // ---------------- v2 = alpha^T @ value2 (8 m-slices x 32 float4 cols) ----
    {
        const int qc    = tid & 31;      // float4 column (4 d's)
        const int slice = tid >> 5;      // 0..7, 128 m each
        const float* vp = value2 + (size_t)bh * QM * QC + (size_t)(slice * 128) * QC + (qc << 2);
        const float* al = logit_s + slice * 128;
        float ax = 0.f, ay = 0.f, az = 0.f, aw = 0.f;
        #pragma unroll 8
        for (int m = 0; m < 128; ++m) {
            float a4 = al[m];
            float4 v = __ldcs((const float4*)(vp + m * QC));
            ax += a4 * v.x; ay += a4 * v.y; az += a4 * v.z; aw += a4 * v.w;
        }
        // partials into wq_s (dead now): [slice][128 d]
        *(float4*)(wq_s + slice * QC + (qc << 2)) = make_float4(ax, ay, az, aw);
    }
    __syncthreads();

    // ---------------- final reduce + channel gate + output ----------------
    if (tid < QC) {
        const int d = tid;
        float v2v = 0.f;
        #pragma unroll
        for (int s = 0; s < 8; ++s) v2v += wq_s[s * QC + d];
        v2v *= inv_se;

        const float* w2 = w_last2 + (h * QMID) * QC + d;
        float pv = 0.f;
        #pragma unroll 8
        for (int o = 0; o < QMID; ++o) pv += pool_s[o] * w2[o * QC];
        float z   = pv + b_last2[h * QC + d];
        float acv = 1.0f / (1.0f + __expf(-z));
        out[bh * QC + d] = value1[bh * QC + d] * v2v * acv;
    }
}

extern "C" void kernel_launch(void* const* d_in, const int* in_sizes, int n_in,
                              void* d_out, int out_size) {
    const float* query    = (const float*)d_in[0];
    const float* key_feat = (const float*)d_in[1];
    const int*   att_mask = (const int*)  d_in[2];
    const float* value1   = (const float*)d_in[3];
    const float* value2   = (const float*)d_in[4];
    const float* w_basic  = (const float*)d_in[5];
    const float* b_basic  = (const float*)d_in[6];
    const float* w_last   = (const float*)d_in[7];
    const float* b_last   = (const float*)d_in[8];
    const float* w_last2  = (const float*)d_in[9];
    const float* b_last2  = (const float*)d_in[10];
    float* out = (float*)d_out;

    const int smem_bytes = SMEM_FLOATS * (int)sizeof(float);
    cudaFuncSetAttribute(scatt_kernel, cudaFuncAttributeMaxDynamicSharedMemorySize, smem_bytes);
    scatt_kernel<<<QB * QH, NTHREADS, smem_bytes>>>(
        query, key_feat, att_mask, value1, value2,
        w_basic, b_basic, w_last, b_last, w_last2, b_last2, out);
}

// round 9
// speedup vs baseline: 1.9499x; 1.7637x over previous
#include <cuda_runtime.h>
#include <cstdint>

// Problem constants
#define QB   64
#define QH   8
#define QM   1024
#define QC   128
#define QMID 64
#define TM   64                   // rows per kf tile (double-buffered)
#define NTHREADS 256

// packed fp32x2 FMA (Blackwell): d = a*b + d on both lanes
__device__ __forceinline__ void ffma2(unsigned long long &d, unsigned long long a, unsigned long long b) {
    asm volatile("fma.rn.f32x2 %0, %1, %2, %0;" : "+l"(d) : "l"(a), "l"(b));
}
__device__ __forceinline__ unsigned long long splat2(float v) {
    unsigned long long r;
    asm("mov.b64 %0, {%1, %1};" : "=l"(r) : "f"(v));
    return r;
}
__device__ __forceinline__ float2 unpack2(unsigned long long v) {
    float2 r;
    asm("mov.b64 {%0, %1}, %2;" : "=f"(r.x), "=f"(r.y) : "l"(v));
    return r;
}
static __device__ __forceinline__ uint32_t smem_u32(const void* p) {
    uint32_t a;
    asm("{ .reg .u64 t; cvta.to.shared.u64 t, %1; cvt.u32.u64 %0, t; }" : "=r"(a) : "l"(p));
    return a;
}
static __device__ __forceinline__ void cp_async16(uint32_t dst, const void* src) {
    asm volatile("cp.async.cg.shared.global [%0], [%1], 16;" :: "r"(dst), "l"(src) : "memory");
}
#define CP_COMMIT() asm volatile("cp.async.commit_group;" ::: "memory")
#define CP_WAIT0()  asm volatile("cp.async.wait_group 0;" ::: "memory")
#define CP_WAIT1()  asm volatile("cp.async.wait_group 1;" ::: "memory")

// dynamic smem layout (floats):
//  wq      : 128*64 = 8192   (phase2: partial buffer 8x128)
//  kf0/kf1 : 2 * 64*128 = 16384
//  logit   : 1024
//  midx    : 1024 (ints)
//  wl/bb/pool : 64*3
//  red     : 128  (q staging)
//  sc      : 48   (warp scratch, gmax, inv_se, wtot[8])
#define SMEM_FLOATS (8192 + 16384 + 1024 + 1024 + 64 + 64 + 64 + 128 + 48)

extern "C" __global__ void __launch_bounds__(NTHREADS, 2)
scatt_kernel(const float* __restrict__ query,
             const float* __restrict__ key_feat,
             const int*   __restrict__ att_mask,
             const float* __restrict__ value1,
             const float* __restrict__ value2,
             const float* __restrict__ w_basic,
             const float* __restrict__ b_basic,
             const float* __restrict__ w_last,
             const float* __restrict__ b_last,
             const float* __restrict__ w_last2,
             const float* __restrict__ b_last2,
             float* __restrict__ out)
{
    extern __shared__ float sm[];
    float* wq_s    = sm;                      // [k][o]  k:128 o:64
    float* kf0_s   = wq_s + 8192;             // buffer 0: 64x128 quad-swizzled
    float* kf1_s   = kf0_s + 8192;            // buffer 1
    float* logit_s = kf1_s + 8192;            // 1024 (compact slots)
    int*   midx_s  = (int*)(logit_s + 1024);  // 1024 compact row indices
    float* wl_s    = (float*)(midx_s + 1024); // 64
    float* bb_s    = wl_s + 64;               // 64
    float* pool_s  = bb_s + 64;               // 64
    float* red_s   = pool_s + 64;             // 128 (q staging)
    float* sc_s    = red_s + 128;             // 48
    int*   wtot_i  = (int*)(sc_s + 36);       // 8 warp totals

    const uint32_t kf0_addr = smem_u32(kf0_s);
    const uint32_t kf1_addr = smem_u32(kf1_s);

    const int tid = threadIdx.x;
    const int wid = tid >> 5;
    const int lid = tid & 31;
    const int bh  = blockIdx.x;
    const int b   = bh >> 3;
    const int h   = bh & 7;

    const float* qp  = query    + bh * QC;
    const float* kfp = key_feat + (size_t)bh * QM * QC;

    // ---------------- mask compaction (prefix scan over 1024 rows) ----------
    // thread t owns rows 4t..4t+3
    midx_s[tid] = 0; midx_s[tid + 256] = 0; midx_s[tid + 512] = 0; midx_s[tid + 768] = 0;

    int mvbits = 0, cnt = 0;
    #pragma unroll
    for (int j = 0; j < 4; ++j) {
        int mv = att_mask[b * QM + (tid << 2) + j];
        mvbits |= mv << j;
        cnt += mv;
    }
    int inc = cnt;
    #pragma unroll
    for (int o = 1; o < 32; o <<= 1) {
        int n = __shfl_up_sync(~0u, inc, o);
        if (lid >= o) inc += n;
    }
    if (lid == 31) wtot_i[wid] = inc;
    __syncthreads();
    int base = 0, nact = 0;
    #pragma unroll
    for (int w = 0; w < 8; ++w) {
        int t8 = wtot_i[w];
        if (w < wid) base += t8;
        nact += t8;
    }
    int pos = base + (inc - cnt);
    __syncthreads();   // zero-init of midx_s visible before scatter
    #pragma unroll
    for (int j = 0; j < 4; ++j) {
        if ((mvbits >> j) & 1) midx_s[pos++] = (tid << 2) + j;
    }

    const int ntiles = (nact + TM - 1) >> 6;

    // other setup
    if (tid < 64) {
        pool_s[tid] = 0.f;
        wl_s[tid]   = w_last[h * QMID + tid];
        bb_s[tid]   = b_basic[h * QMID + tid];
    }
    for (int i = tid; i < QC; i += NTHREADS) red_s[i] = qp[i];
    __syncthreads();   // midx ready for staging; red ready for wq

    // stage one 64-row gathered tile; swizzle key = (m>>2)&7
    #define STAGE_TILE(TILE, BUFADDR)                                              \
        {                                                                          \
            const int _t0 = (TILE) * TM;                                           \
            _Pragma("unroll")                                                      \
            for (int _it = 0; _it < 8; ++_it) {                                    \
                int _f  = tid + _it * NTHREADS;                                    \
                int _m  = _f >> 5;                                                 \
                int _qk = _f & 31;                                                 \
                int _qs = _qk ^ ((_m >> 2) & 7);                                   \
                int _src_row = midx_s[_t0 + _m];                                   \
                cp_async16((BUFADDR) + (uint32_t)((( _m << 7) + (_qs << 2)) << 2), \
                           kfp + ((size_t)_src_row << 7) + (_qk << 2));            \
            }                                                                      \
            CP_COMMIT();                                                           \
        }

    // prefetch tile 0 (overlaps wq build)
    if (ntiles > 0) STAGE_TILE(0, kf0_addr);

    // wq[k][o] = q[k] * w_basic[h][k][o]
    for (int i = tid; i < QC * QMID; i += NTHREADS) {
        int k = i >> 6;
        wq_s[i] = red_s[k] * w_basic[(h * QC + k) * QMID + (i & 63)];
    }

    const float blast = b_last[h];

    // thread decomposition: 16 rowgroups (x4 rows) x 16 colgroups (x4 cols), full k
    const int rw = tid >> 4;        // 0..15 -> rows rw*4..rw*4+3
    const int cw = tid & 15;        // 0..15 -> cols cw*4..cw*4+3
    const int xc = rw & 7;          // A swizzle key

    __syncthreads();   // wq ready before GEMM reads it

    float bb4[4], wl4[4];
    #pragma unroll
    for (int j = 0; j < 4; ++j) {
        bb4[j] = bb_s[(cw << 2) + j];
        wl4[j] = wl_s[(cw << 2) + j];
    }
    float pp[4] = {0.f, 0.f, 0.f, 0.f};

    const float* wb = wq_s + (cw << 2);

    // ---------------- main tiles (double-buffered, compacted rows) ----------
    for (int tile = 0; tile < ntiles; ++tile) {
        const float* buf = (tile & 1) ? kf1_s : kf0_s;

        if (tile + 1 < ntiles) {
            STAGE_TILE(tile + 1, (tile & 1) ? kf0_addr : kf1_addr);
            CP_WAIT1();
        } else {
            CP_WAIT0();
        }
        __syncthreads();

        // full-k GEMM: 4 rows x 4 cols per thread, 32 k-quads
        unsigned long long acc[4][2];
        #pragma unroll
        for (int r = 0; r < 4; ++r) { acc[r][0] = 0ULL; acc[r][1] = 0ULL; }

        const float* kfb = buf + (rw << 9);

        #pragma unroll 2
        for (int qq = 0; qq < 32; ++qq) {
            ulonglong2 bv[4];
            #pragma unroll
            for (int j = 0; j < 4; ++j)
                bv[j] = *(const ulonglong2*)(wb + ((qq << 2) + j) * QMID);

            float4 a[4];
            const int qs4 = ((qq ^ xc) << 2);
            #pragma unroll
            for (int r = 0; r < 4; ++r)
                a[r] = *(const float4*)(kfb + (r << 7) + qs4);

            #pragma unroll
            for (int j = 0; j < 4; ++j) {
                #pragma unroll
                for (int r = 0; r < 4; ++r) {
                    float av = (j == 0) ? a[r].x : (j == 1) ? a[r].y : (j == 2) ? a[r].z : a[r].w;
                    unsigned long long ap = splat2(av);
                    ffma2(acc[r][0], ap, bv[j].x);
                    ffma2(acc[r][1], ap, bv[j].y);
                }
            }
        }

        // register epilogue: all gathered rows are active (mask=1); range-check pad
        #pragma unroll
        for (int r = 0; r < 4; ++r) {
            const int mg = tile * TM + (rw << 2) + r;
            const float vld = (mg < nact) ? 1.f : 0.f;
            float2 lo = unpack2(acc[r][0]);
            float2 hi = unpack2(acc[r][1]);
            float x0 = fmaxf(lo.x + bb4[0], 0.f);
            float x1 = fmaxf(lo.y + bb4[1], 0.f);
            float x2 = fmaxf(hi.x + bb4[2], 0.f);
            float x3 = fmaxf(hi.y + bb4[3], 0.f);
            pp[0] += x0 * vld; pp[1] += x1 * vld; pp[2] += x2 * vld; pp[3] += x3 * vld;
            float lp = x0 * wl4[0] + x1 * wl4[1] + x2 * wl4[2] + x3 * wl4[3];
            lp += __shfl_xor_sync(~0u, lp, 1);
            lp += __shfl_xor_sync(~0u, lp, 2);
            lp += __shfl_xor_sync(~0u, lp, 4);
            lp += __shfl_xor_sync(~0u, lp, 8);
            if (cw == 0 && mg < nact) logit_s[mg] = lp + blast;
        }
        __syncthreads();
    }

    // pool accumulation
    #pragma unroll
    for (int j = 0; j < 4; ++j) {
        float v = pp[j];
        v += __shfl_xor_sync(~0u, v, 16);
        if (lid < 16) atomicAdd(&pool_s[(cw << 2) + j], v);
    }
    __syncthreads();

    // ---------------- softmax over compact logits [0, nact) ----------------
    const float cnt_inv = 1.0f / (float)nact;
    if (tid < 64) pool_s[tid] *= cnt_inv;

    float lm = -3.4e38f;
    for (int i = tid; i < nact; i += NTHREADS) lm = fmaxf(lm, logit_s[i]);
    #pragma unroll
    for (int o = 16; o; o >>= 1) lm = fmaxf(lm, __shfl_xor_sync(~0u, lm, o));
    if (lid == 0) sc_s[wid] = lm;
    __syncthreads();
    if (tid < 32) {
        float v = (tid < 8) ? sc_s[tid] : -3.4e38f;
        #pragma unroll
        for (int o = 4; o; o >>= 1) v = fmaxf(v, __shfl_xor_sync(~0u, v, o));
        if (tid == 0) sc_s[32] = v;
    }
    __syncthreads();
    const float gmax = sc_s[32];

    float se = 0.f;
    for (int i = tid; i < nact; i += NTHREADS) {
        float e = __expf(logit_s[i] - gmax);
        logit_s[i] = e;
        se += e;
    }
    #pragma unroll
    for (int o = 16; o; o >>= 1) se += __shfl_xor_sync(~0u, se, o);
    if (lid == 0) sc_s[wid] = se;
    __syncthreads();
    if (tid < 32) {
        float v = (tid < 8) ? sc_s[tid] : 0.f;
        #pragma unroll
        for (int o = 4; o; o >>= 1) v += __shfl_xor_sync(~0u, v, o);
        if (tid == 0) sc_s[33] = 1.0f / v;
    }
    __syncthreads();
    const float inv_se = sc_s[33];

    // ---------------- v2 = alpha^T @ value2 over ACTIVE rows only ------------
    {
        const int qc    = tid & 31;      // float4 column (4 d's)
        const int slice = tid >> 5;      // 0..7
        const float* vbase = value2 + (size_t)bh * QM * QC + (qc << 2);
        float ax = 0.f, ay = 0.f, az = 0.f, aw = 0.f;
        #pragma unroll 4
        for (int i = slice; i < nact; i += 8) {
            float a4 = logit_s[i];
            int msrc = midx_s[i];
            float4 v = __ldcs((const float4*)(vbase + ((size_t)msrc << 7)));
            ax += a4 * v.x; ay += a4 * v.y; az += a4 * v.z; aw += a4 * v.w;
        }
        *(float4*)(wq_s + slice * QC + (qc << 2)) = make_float4(ax, ay, az, aw);
    }
    __syncthreads();

    // ---------------- final reduce + channel gate + output ----------------
    if (tid < QC) {
        const int d = tid;
        float v2v = 0.f;
        #pragma unroll
        for (int s = 0; s < 8; ++s) v2v += wq_s[s * QC + d];
        v2v *= inv_se;

        const float* w2 = w_last2 + (h * QMID) * QC + d;
        float pv = 0.f;
        #pragma unroll 8
        for (int o = 0; o < QMID; ++o) pv += pool_s[o] * w2[o * QC];
        float z   = pv + b_last2[h * QC + d];
        float acv = 1.0f / (1.0f + __expf(-z));
        out[bh * QC + d] = value1[bh * QC + d] * v2v * acv;
    }
}

extern "C" void kernel_launch(void* const* d_in, const int* in_sizes, int n_in,
                              void* d_out, int out_size) {
    const float* query    = (const float*)d_in[0];
    const float* key_feat = (const float*)d_in[1];
    const int*   att_mask = (const int*)  d_in[2];
    const float* value1   = (const float*)d_in[3];
    const float* value2   = (const float*)d_in[4];
    const float* w_basic  = (const float*)d_in[5];
    const float* b_basic  = (const float*)d_in[6];
    const float* w_last   = (const float*)d_in[7];
    const float* b_last   = (const float*)d_in[8];
    const float* w_last2  = (const float*)d_in[9];
    const float* b_last2  = (const float*)d_in[10];
    float* out = (float*)d_out;

    const int smem_bytes = SMEM_FLOATS * (int)sizeof(float);
    cudaFuncSetAttribute(scatt_kernel, cudaFuncAttributeMaxDynamicSharedMemorySize, smem_bytes);
    scatt_kernel<<<QB * QH, NTHREADS, smem_bytes>>>(
        query, key_feat, att_mask, value1, value2,
        w_basic, b_basic, w_last, b_last, w_last2, b_last2, out);
}

// round 10
// speedup vs baseline: 2.0293x; 1.0407x over previous
#include <cuda_runtime.h>
#include <cstdint>

// Problem constants
#define QB   64
#define QH   8
#define QM   1024
#define QC   128
#define QMID 64
#define TM   64                   // rows per tile (one tile per group in flight)
#define NTHREADS 256

__device__ __forceinline__ void ffma2(unsigned long long &d, unsigned long long a, unsigned long long b) {
    asm volatile("fma.rn.f32x2 %0, %1, %2, %0;" : "+l"(d) : "l"(a), "l"(b));
}
__device__ __forceinline__ unsigned long long splat2(float v) {
    unsigned long long r;
    asm("mov.b64 %0, {%1, %1};" : "=l"(r) : "f"(v));
    return r;
}
__device__ __forceinline__ float2 unpack2(unsigned long long v) {
    float2 r;
    asm("mov.b64 {%0, %1}, %2;" : "=f"(r.x), "=f"(r.y) : "l"(v));
    return r;
}
static __device__ __forceinline__ uint32_t smem_u32(const void* p) {
    uint32_t a;
    asm("{ .reg .u64 t; cvta.to.shared.u64 t, %1; cvt.u32.u64 %0, t; }" : "=r"(a) : "l"(p));
    return a;
}
static __device__ __forceinline__ void cp_async16(uint32_t dst, const void* src) {
    asm volatile("cp.async.cg.shared.global [%0], [%1], 16;" :: "r"(dst), "l"(src) : "memory");
}
#define CP_COMMIT() asm volatile("cp.async.commit_group;" ::: "memory")
#define CP_WAIT0()  asm volatile("cp.async.wait_group 0;" ::: "memory")
#define BAR_GROUP(ID) asm volatile("bar.sync %0, 128;" :: "r"(ID) : "memory")

// dynamic smem layout (floats):
//  wq      : 128*64 = 8192   (phase2: partial buffer 8x128)
//  kf0/kf1 : 2 * 64*128 = 16384   (one per group)
//  logit   : 1024
//  midx    : 1024 (ints)
//  wl/bb/pool : 64*3
//  red     : 128
//  sc      : 48
#define SMEM_FLOATS (8192 + 16384 + 1024 + 1024 + 64 + 64 + 64 + 128 + 48)

extern "C" __global__ void __launch_bounds__(NTHREADS, 2)
scatt_kernel(const float* __restrict__ query,
             const float* __restrict__ key_feat,
             const int*   __restrict__ att_mask,
             const float* __restrict__ value1,
             const float* __restrict__ value2,
             const float* __restrict__ w_basic,
             const float* __restrict__ b_basic,
             const float* __restrict__ w_last,
             const float* __restrict__ b_last,
             const float* __restrict__ w_last2,
             const float* __restrict__ b_last2,
             float* __restrict__ out)
{
    extern __shared__ float sm[];
    float* wq_s    = sm;                      // [k][o]  k:128 o:64
    float* kf0_s   = wq_s + 8192;             // group-0 buffer: 64x128 quad-swizzled
    float* kf1_s   = kf0_s + 8192;            // group-1 buffer
    float* logit_s = kf1_s + 8192;            // 1024 (compact slots)
    int*   midx_s  = (int*)(logit_s + 1024);  // 1024 compact row indices
    float* wl_s    = (float*)(midx_s + 1024); // 64
    float* bb_s    = wl_s + 64;               // 64
    float* pool_s  = bb_s + 64;               // 64
    float* red_s   = pool_s + 64;             // 128 (q staging)
    float* sc_s    = red_s + 128;             // 48
    int*   wtot_i  = (int*)(sc_s + 36);       // 8 warp totals

    const int tid = threadIdx.x;
    const int wid = tid >> 5;
    const int lid = tid & 31;
    const int bh  = blockIdx.x;
    const int b   = bh >> 3;
    const int h   = bh & 7;

    const float* qp  = query    + bh * QC;
    const float* kfp = key_feat + (size_t)bh * QM * QC;

    // ---------------- mask compaction (prefix scan over 1024 rows) ----------
    midx_s[tid] = 0; midx_s[tid + 256] = 0; midx_s[tid + 512] = 0; midx_s[tid + 768] = 0;

    int mvbits = 0, cnt = 0;
    #pragma unroll
    for (int j = 0; j < 4; ++j) {
        int mv = att_mask[b * QM + (tid << 2) + j];
        mvbits |= mv << j;
        cnt += mv;
    }
    int inc = cnt;
    #pragma unroll
    for (int o = 1; o < 32; o <<= 1) {
        int n = __shfl_up_sync(~0u, inc, o);
        if (lid >= o) inc += n;
    }
    if (lid == 31) wtot_i[wid] = inc;
    __syncthreads();
    int base = 0, nact = 0;
    #pragma unroll
    for (int w = 0; w < 8; ++w) {
        int t8 = wtot_i[w];
        if (w < wid) base += t8;
        nact += t8;
    }
    int pos = base + (inc - cnt);
    __syncthreads();
    #pragma unroll
    for (int j = 0; j < 4; ++j) {
        if ((mvbits >> j) & 1) midx_s[pos++] = (tid << 2) + j;
    }

    const int ntiles = (nact + TM - 1) >> 6;

    if (tid < 64) {
        pool_s[tid] = 0.f;
        wl_s[tid]   = w_last[h * QMID + tid];
        bb_s[tid]   = b_basic[h * QMID + tid];
    }
    for (int i = tid; i < QC; i += NTHREADS) red_s[i] = qp[i];
    __syncthreads();   // midx ready for staging

    // group decomposition
    const int g   = tid >> 7;         // 0 or 1
    const int gt  = tid & 127;        // thread within group
    const int rg  = gt >> 4;          // 0..7 -> rows rg*8..rg*8+7
    const int cg  = gt & 15;          // 0..15 -> cols cg*4..cg*4+3
    const uint32_t mybuf_addr = smem_u32(g ? kf1_s : kf0_s);
    const float*   mybuf      = g ? kf1_s : kf0_s;
    const int      barid      = 1 + g;

    // stage one gathered 64-row tile into this group's buffer (128 threads, 16 iters)
    #define STAGE_TILE_G(TILE)                                                     \
        {                                                                          \
            const int _t0 = (TILE) * TM;                                           \
            _Pragma("unroll")                                                      \
            for (int _it = 0; _it < 16; ++_it) {                                   \
                int _f  = gt + _it * 128;                                          \
                int _m  = _f >> 5;                                                 \
                int _qk = _f & 31;                                                 \
                int _qs = _qk ^ ((_m >> 2) & 7);                                   \
                int _src_row = midx_s[_t0 + _m];                                   \
                cp_async16(mybuf_addr + (uint32_t)(((_m << 7) + (_qs << 2)) << 2), \
                           kfp + ((size_t)_src_row << 7) + (_qk << 2));            \
            }                                                                      \
            CP_COMMIT();                                                           \
        }

    // each group prefetches its first tile (overlaps wq build)
    if (g < ntiles) STAGE_TILE_G(g);

    // wq[k][o] = q[k] * w_basic[h][k][o]
    for (int i = tid; i < QC * QMID; i += NTHREADS) {
        int k = i >> 6;
        wq_s[i] = red_s[k] * w_basic[(h * QC + k) * QMID + (i & 63)];
    }
    const float blast = b_last[h];
    __syncthreads();   // wq ready

    float bb4[4], wl4[4];
    #pragma unroll
    for (int j = 0; j < 4; ++j) {
        bb4[j] = bb_s[(cg << 2) + j];
        wl4[j] = wl_s[(cg << 2) + j];
    }
    float pp[4] = {0.f, 0.f, 0.f, 0.f};

    const float* wb  = wq_s + (cg << 2);
    const float* kfb = mybuf + (rg << 10);    // rg*8 rows * 128

    // ---------------- main tiles: group g handles tiles g, g+2, ... ----------
    for (int tile = g; tile < ntiles; tile += 2) {
        CP_WAIT0();
        BAR_GROUP(barid);

        // full-k GEMM: 8 rows x 4 cols per thread, 32 k-quads
        unsigned long long acc[8][2];
        #pragma unroll
        for (int r = 0; r < 8; ++r) { acc[r][0] = 0ULL; acc[r][1] = 0ULL; }

        #pragma unroll 2
        for (int qq = 0; qq < 32; ++qq) {
            ulonglong2 bv[4];
            #pragma unroll
            for (int j = 0; j < 4; ++j)
                bv[j] = *(const ulonglong2*)(wb + ((qq << 2) + j) * QMID);

            #pragma unroll
            for (int half = 0; half < 2; ++half) {
                const int qs4 = ((qq ^ (((rg << 1) + half) & 7)) << 2);
                float4 a[4];
                #pragma unroll
                for (int r = 0; r < 4; ++r)
                    a[r] = *(const float4*)(kfb + (((half << 2) + r) << 7) + qs4);

                #pragma unroll
                for (int j = 0; j < 4; ++j) {
                    #pragma unroll
                    for (int r = 0; r < 4; ++r) {
                        float av = (j == 0) ? a[r].x : (j == 1) ? a[r].y : (j == 2) ? a[r].z : a[r].w;
                        unsigned long long ap = splat2(av);
                        const int rr = (half << 2) + r;
                        ffma2(acc[rr][0], ap, bv[j].x);
                        ffma2(acc[rr][1], ap, bv[j].y);
                    }
                }
            }
        }

        BAR_GROUP(barid);   // group's reads of its buffer done

        // issue staging for this group's next tile (overlaps epilogue + other group)
        if (tile + 2 < ntiles) STAGE_TILE_G(tile + 2);

        // register epilogue (all gathered rows active; pad range-checked)
        #pragma unroll
        for (int r = 0; r < 8; ++r) {
            const int mg = tile * TM + (rg << 3) + r;
            const float vld = (mg < nact) ? 1.f : 0.f;
            float2 lo = unpack2(acc[r][0]);
            float2 hi = unpack2(acc[r][1]);
            float x0 = fmaxf(lo.x + bb4[0], 0.f);
            float x1 = fmaxf(lo.y + bb4[1], 0.f);
            float x2 = fmaxf(hi.x + bb4[2], 0.f);
            float x3 = fmaxf(hi.y + bb4[3], 0.f);
            pp[0] += x0 * vld; pp[1] += x1 * vld; pp[2] += x2 * vld; pp[3] += x3 * vld;
            float lp = x0 * wl4[0] + x1 * wl4[1] + x2 * wl4[2] + x3 * wl4[3];
            lp += __shfl_xor_sync(~0u, lp, 1);
            lp += __shfl_xor_sync(~0u, lp, 2);
            lp += __shfl_xor_sync(~0u, lp, 4);
            lp += __shfl_xor_sync(~0u, lp, 8);
            if (cg == 0 && mg < nact) logit_s[mg] = lp + blast;
        }
    }

    // pool accumulation: lanes l and l+16 share cg -> combine, then atomics
    #pragma unroll
    for (int j = 0; j < 4; ++j) {
        float v = pp[j];
        v += __shfl_xor_sync(~0u, v, 16);
        if (lid < 16) atomicAdd(&pool_s[(cg << 2) + j], v);
    }
    __syncthreads();

    // ---------------- softmax over compact logits [0, nact) ----------------
    const float cnt_inv = 1.0f / (float)nact;
    if (tid < 64) pool_s[tid] *= cnt_inv;

    float lm = -3.4e38f;
    for (int i = tid; i < nact; i += NTHREADS) lm = fmaxf(lm, logit_s[i]);
    #pragma unroll
    for (int o = 16; o; o >>= 1) lm = fmaxf(lm, __shfl_xor_sync(~0u, lm, o));
    if (lid == 0) sc_s[wid] = lm;
    __syncthreads();
    if (tid < 32) {
        float v = (tid < 8) ? sc_s[tid] : -3.4e38f;
        #pragma unroll
        for (int o = 4; o; o >>= 1) v = fmaxf(v, __shfl_xor_sync(~0u, v, o));
        if (tid == 0) sc_s[32] = v;
    }
    __syncthreads();
    const float gmax = sc_s[32];

    float se = 0.f;
    for (int i = tid; i < nact; i += NTHREADS) {
        float e = __expf(logit_s[i] - gmax);
        logit_s[i] = e;
        se += e;
    }
    #pragma unroll
    for (int o = 16; o; o >>= 1) se += __shfl_xor_sync(~0u, se, o);
    if (lid == 0) sc_s[wid] = se;
    __syncthreads();
    if (tid < 32) {
        float v = (tid < 8) ? sc_s[tid] : 0.f;
        #pragma unroll
        for (int o = 4; o; o >>= 1) v += __shfl_xor_sync(~0u, v, o);
        if (tid == 0) sc_s[33] = 1.0f / v;
    }
    __syncthreads();
    const float inv_se = sc_s[33];

    // ---------------- v2 = alpha^T @ value2 over ACTIVE rows only ------------
    {
        const int qc    = tid & 31;
        const int slice = tid >> 5;
        const float* vbase = value2 + (size_t)bh * QM * QC + (qc << 2);
        float ax = 0.f, ay = 0.f, az = 0.f, aw = 0.f;
        #pragma unroll 4
        for (int i = slice; i < nact; i += 8) {
            float a4 = logit_s[i];
            int msrc = midx_s[i];
            float4 v = __ldcs((const float4*)(vbase + ((size_t)msrc << 7)));
            ax += a4 * v.x; ay += a4 * v.y; az += a4 * v.z; aw += a4 * v.w;
        }
        *(float4*)(wq_s + slice * QC + (qc << 2)) = make_float4(ax, ay, az, aw);
    }
    __syncthreads();

    // ---------------- final reduce + channel gate + output ----------------
    if (tid < QC) {
        const int d = tid;
        float v2v = 0.f;
        #pragma unroll
        for (int s = 0; s < 8; ++s) v2v += wq_s[s * QC + d];
        v2v *= inv_se;

        const float* w2 = w_last2 + (h * QMID) * QC + d;
        float pv = 0.f;
        #pragma unroll 8
        for (int o = 0; o < QMID; ++o) pv += pool_s[o] * w2[o * QC];
        float z   = pv + b_last2[h * QC + d];
        float acv = 1.0f / (1.0f + __expf(-z));
        out[bh * QC + d] = value1[bh * QC + d] * v2v * acv;
    }
}

extern "C" void kernel_launch(void* const* d_in, const int* in_sizes, int n_in,
                              void* d_out, int out_size) {
    const float* query    = (const float*)d_in[0];
    const float* key_feat = (const float*)d_in[1];
    const int*   att_mask = (const int*)  d_in[2];
    const float* value1   = (const float*)d_in[3];
    const float* value2   = (const float*)d_in[4];
    const float* w_basic  = (const float*)d_in[5];
    const float* b_basic  = (const float*)d_in[6];
    const float* w_last   = (const float*)d_in[7];
    const float* b_last   = (const float*)d_in[8];
    const float* w_last2  = (const float*)d_in[9];
    const float* b_last2  = (const float*)d_in[10];
    float* out = (float*)d_out;

    const int smem_bytes = SMEM_FLOATS * (int)sizeof(float);
    cudaFuncSetAttribute(scatt_kernel, cudaFuncAttributeMaxDynamicSharedMemorySize, smem_bytes);
    scatt_kernel<<<QB * QH, NTHREADS, smem_bytes>>>(
        query, key_feat, att_mask, value1, value2,
        w_basic, b_basic, w_last, b_last, w_last2, b_last2, out);
}